// round 11
// baseline (speedup 1.0000x reference)
#include <cuda_runtime.h>
#include <cstdint>

#define B_SZ 1024
#define T_SZ 512
#define F_SZ 124
#define NROWS (B_SZ * T_SZ)

// Pre-activations of layer0, [t][b] as float4 (xyz = hidden, w = pad). 8.4MB -> L2.
__device__ float4 g_pre[NROWS];

__device__ __forceinline__ float tanha(float v) {
    float r;
    asm("tanh.approx.f32 %0, %1;" : "=f"(r) : "f"(v));
    return r;
}
__device__ __forceinline__ void cp_async16(unsigned int saddr, const void* gptr) {
    asm volatile("cp.async.cg.shared.global [%0], [%1], 16;" :: "r"(saddr), "l"(gptr));
}
#define CP_COMMIT() asm volatile("cp.async.commit_group;" ::: "memory")
#define CP_WAIT1()  asm volatile("cp.async.wait_group 1;"  ::: "memory")

// packed f32x2 helpers (FFMA2 — only reachable via PTX fma.rn.f32x2)
typedef unsigned long long ull;
__device__ __forceinline__ ull pk2(float lo, float hi) {
    ull r; asm("mov.b64 %0, {%1, %2};" : "=l"(r) : "f"(lo), "f"(hi)); return r;
}
__device__ __forceinline__ void unpk2(float& lo, float& hi, ull v) {
    asm("mov.b64 {%0, %1}, %2;" : "=f"(lo), "=f"(hi) : "l"(v));
}
__device__ __forceinline__ ull fma2(ull a, ull b, ull c) {
    ull d; asm("fma.rn.f32x2 %0, %1, %2, %3;" : "=l"(d) : "l"(a), "l"(b), "l"(c)); return d;
}

// ---------------------------------------------------------------------------
// Kernel A: pre[t][b][i] = dot(x[b,t,:], W_ih0[i,:]) + biases.
// cp.async double-buffered: chunk k+2 streams in while chunk k computes,
// so DRAM is never idle. 256 threads / 256 rows per block.
// ---------------------------------------------------------------------------
extern __shared__ float s2[];            // [2][256*36] = 73728 B dynamic

__global__ __launch_bounds__(256) void pre_kernel(
    const float* __restrict__ x,
    const float* __restrict__ Wih0,
    const float* __restrict__ bih0,
    const float* __restrict__ bhh0)
{
    __shared__ float sW[3 * 128];        // W_ih0 zero-padded to 128 cols

    const int tid  = threadIdx.x;
    const int row0 = blockIdx.x * 256;
    const int lane = tid & 31;
    const int lrbase = (tid >> 5) * 32 + (lane >> 3);
    const int c4     = lane & 7;
    const float4* __restrict__ x4 = (const float4*)x;   // row stride 31 float4

#define STAGE_PRE(bufidx, kc, nc4)                                         \
    if (c4 < (nc4)) {                                                      \
        _Pragma("unroll")                                                  \
        for (int it = 0; it < 8; it++) {                                   \
            const int lr = lrbase + it * 4;                                \
            unsigned int sa = (unsigned int)__cvta_generic_to_shared(      \
                &s2[(bufidx) * 9216 + lr * 36 + c4 * 4]);                  \
            cp_async16(sa, &x4[(row0 + lr) * 31 + ((kc) >> 2) + c4]);      \
        }                                                                  \
    }

    // Start DRAM traffic immediately: chunks 0 and 1 in flight.
    STAGE_PRE(0, 0, 8);  CP_COMMIT();
    STAGE_PRE(1, 32, 8); CP_COMMIT();

    for (int idx = tid; idx < 3 * 128; idx += 256) {
        int i = idx >> 7, cc = idx & 127;
        sW[idx] = (cc < F_SZ) ? Wih0[i * F_SZ + cc] : 0.0f;
    }
    const float bs0 = bih0[0] + bhh0[0];
    const float bs1 = bih0[1] + bhh0[1];
    const float bs2 = bih0[2] + bhh0[2];
    __syncthreads();

    float acc0 = 0.f, acc1 = 0.f, acc2 = 0.f;

    #pragma unroll
    for (int ci = 0; ci < 4; ci++) {
        const int kc  = ci * 32;
        const int nc4 = (ci == 3) ? 7 : 8;

        CP_WAIT1();          // chunk ci complete (ci+1 may still be in flight)
        __syncwarp();        // other lanes' cp.async writes visible

        const float* sb = &s2[(ci & 1) * 9216];
        #pragma unroll
        for (int cc = 0; cc < 8; cc++) {
            if (cc < nc4) {
                float4 v  = *(const float4*)&sb[tid * 36 + cc * 4];
                float4 w0 = *(const float4*)&sW[0 * 128 + kc + cc * 4];
                float4 w1 = *(const float4*)&sW[1 * 128 + kc + cc * 4];
                float4 w2 = *(const float4*)&sW[2 * 128 + kc + cc * 4];
                acc0 += v.x * w0.x + v.y * w0.y + v.z * w0.z + v.w * w0.w;
                acc1 += v.x * w1.x + v.y * w1.y + v.z * w1.z + v.w * w1.w;
                acc2 += v.x * w2.x + v.y * w2.y + v.z * w2.z + v.w * w2.w;
            }
        }
        __syncwarp();        // compute done before re-staging this buffer

        if (ci < 2) {
            const int kn = (ci + 2) * 32;
            const int nn = (ci + 2 == 3) ? 7 : 8;
            STAGE_PRE(ci & 1, kn, nn);
        }
        CP_COMMIT();         // possibly-empty group keeps wait counts aligned
    }

    const int row = row0 + tid;         // row = b*T + t
    const int b   = row >> 9;
    const int t   = row & 511;
    g_pre[t * B_SZ + b] = make_float4(acc0 + bs0, acc1 + bs1, acc2 + bs2, 0.0f);
}
#undef STAGE_PRE

// ---------------------------------------------------------------------------
// Kernel B: layer-split recurrence. 32 blocks x 64 threads.
//   warp 0 (A): layer-0 recurrence (h0 never reads h1), self-feeds pre
//               chunks via cp.async 3-stage ring, writes n0 chunks to nRing.
//   warp 1 (B): layer-1 recurrence one chunk behind (fma.rn.f32x2 packed),
//               + final fc.
// One __syncthreads per 16-step chunk.
// ---------------------------------------------------------------------------
#define CH    16
#define NCHK  (T_SZ / CH)               // 32

__global__ __launch_bounds__(64) void rnn_kernel(
    const float* __restrict__ Whh0,
    const float* __restrict__ Wih1,
    const float* __restrict__ Whh1,
    const float* __restrict__ bih1,
    const float* __restrict__ bhh1,
    const float* __restrict__ Wfc,
    const float* __restrict__ bfc,
    float* __restrict__ out)
{
    __shared__ float4 preRing[3 * CH * 32];   // 24 KB
    __shared__ float4 nRing[2 * CH * 32];     // 16 KB

    const int tid  = threadIdx.x;
    const int lane = tid & 31;
    const bool isA = (tid < 32);
    const int b    = blockIdx.x * 32 + lane;

    // ---- per-role register state ----
    float a0,a1,a2,a3,a4,a5,a6,a7,a8;                 // A: Whh0
    float h0x=0.f, h0y=0.f, h0z=0.f;
    ull Dx01=0, Dy01=0, Dz01=0, Cx01=0, Cy01=0, Cz01=0, BB01=0;   // B packed
    float d6=0,d7=0,d8=0,c6=0,c7=0,c8=0,bb2=0;
    ull hx2=0, hy2=0, hz2=0;
    float h1x=0.f, h1y=0.f, h1z=0.f;

    if (isA) {
        a0=Whh0[0]; a1=Whh0[1]; a2=Whh0[2];
        a3=Whh0[3]; a4=Whh0[4]; a5=Whh0[5];
        a6=Whh0[6]; a7=Whh0[7]; a8=Whh0[8];
        // prologue: chunks 0,1 in flight (each lane stages only its own column)
        #pragma unroll
        for (int c = 0; c < 2; c++) {
            #pragma unroll
            for (int s = 0; s < CH; s++) {
                unsigned int sa = (unsigned int)__cvta_generic_to_shared(
                    &preRing[(c * CH + s) * 32 + lane]);
                cp_async16(sa, &g_pre[(c * CH + s) * B_SZ + b]);
            }
            CP_COMMIT();
        }
    } else {
        const float bb0 = bih1[0] + bhh1[0];
        const float bb1 = bih1[1] + bhh1[1];
        bb2 = bih1[2] + bhh1[2];
        Dx01 = pk2(Whh1[0], Whh1[3]);  Dy01 = pk2(Whh1[1], Whh1[4]);  Dz01 = pk2(Whh1[2], Whh1[5]);
        Cx01 = pk2(Wih1[0], Wih1[3]);  Cy01 = pk2(Wih1[1], Wih1[4]);  Cz01 = pk2(Wih1[2], Wih1[5]);
        BB01 = pk2(bb0, bb1);
        d6 = Whh1[6]; d7 = Whh1[7]; d8 = Whh1[8];
        c6 = Wih1[6]; c7 = Wih1[7]; c8 = Wih1[8];
        hx2 = pk2(0.f, 0.f); hy2 = hx2; hz2 = hx2;
    }

    for (int c = 0; c <= NCHK; c++) {
        if (isA && c < NCHK) CP_WAIT1();     // chunk c arrived (self-staged)
        __syncthreads();                     // publish nRing chunk c-1 to B; recycle bufs

        if (isA) {
            if (c < NCHK) {
                const float4* pr = &preRing[(c % 3) * CH * 32];
                float4*       nw = &nRing[(c & 1) * CH * 32];
                #pragma unroll
                for (int s = 0; s < CH; s++) {
                    const float4 p = pr[s * 32 + lane];
                    const float n0x = tanha(p.x + a0*h0x + a1*h0y + a2*h0z);
                    const float n0y = tanha(p.y + a3*h0x + a4*h0y + a5*h0z);
                    const float n0z = tanha(p.z + a6*h0x + a7*h0y + a8*h0z);
                    nw[s * 32 + lane] = make_float4(n0x, n0y, n0z, 0.f);
                    h0x = n0x; h0y = n0y; h0z = n0z;
                }
                const int cn = c + 2;
                if (cn < NCHK) {
                    #pragma unroll
                    for (int s = 0; s < CH; s++) {
                        unsigned int sa = (unsigned int)__cvta_generic_to_shared(
                            &preRing[((cn % 3) * CH + s) * 32 + lane]);
                        cp_async16(sa, &g_pre[(cn * CH + s) * B_SZ + b]);
                    }
                }
                CP_COMMIT();
            }
        } else if (c >= 1) {
            const float4* nr = &nRing[((c - 1) & 1) * CH * 32];
            #pragma unroll
            for (int s = 0; s < CH; s++) {
                const float4 p = nr[s * 32 + lane];
                const ull px2 = pk2(p.x, p.x);
                const ull py2 = pk2(p.y, p.y);
                const ull pz2 = pk2(p.z, p.z);
                ull T = fma2(Dx01, hx2, BB01);
                T = fma2(Dy01, hy2, T);
                T = fma2(Dz01, hz2, T);
                T = fma2(Cx01, px2, T);
                T = fma2(Cy01, py2, T);
                T = fma2(Cz01, pz2, T);
                float t2 = bb2 + d6*h1x + d7*h1y + d8*h1z;
                t2 += c6*p.x + c7*p.y + c8*p.z;
                float t0, t1; unpk2(t0, t1, T);
                h1x = tanha(t0); h1y = tanha(t1); h1z = tanha(t2);
                hx2 = pk2(h1x, h1x); hy2 = pk2(h1y, h1y); hz2 = pk2(h1z, h1z);
            }
        }
    }

    if (!isA) {
        #pragma unroll
        for (int o = 0; o < 6; o++) {
            out[b * 6 + o] = bfc[o] + Wfc[o * 3 + 0] * h1x
                                    + Wfc[o * 3 + 1] * h1y
                                    + Wfc[o * 3 + 2] * h1z;
        }
    }
}

extern "C" void kernel_launch(void* const* d_in, const int* in_sizes, int n_in,
                              void* d_out, int out_size)
{
    (void)in_sizes; (void)n_in; (void)out_size;
    const float* x    = (const float*)d_in[0];
    const float* Wih0 = (const float*)d_in[1];
    const float* Whh0 = (const float*)d_in[2];
    const float* bih0 = (const float*)d_in[3];
    const float* bhh0 = (const float*)d_in[4];
    const float* Wih1 = (const float*)d_in[5];
    const float* Whh1 = (const float*)d_in[6];
    const float* bih1 = (const float*)d_in[7];
    const float* bhh1 = (const float*)d_in[8];
    const float* Wfc  = (const float*)d_in[9];
    const float* bfc  = (const float*)d_in[10];
    float* out = (float*)d_out;

    // Idempotent, not stream-ordered, safe under graph capture; called every
    // time (no static guard — harness forbids call-count-dependent behavior).
    const int pre_smem = 2 * 256 * 36 * sizeof(float);   // 73728 B
    cudaFuncSetAttribute(pre_kernel, cudaFuncAttributeMaxDynamicSharedMemorySize, pre_smem);

    pre_kernel<<<NROWS / 256, 256, pre_smem>>>(x, Wih0, bih0, bhh0);
    rnn_kernel<<<B_SZ / 32, 64>>>(Whh0, Wih1, Whh1, bih1, bhh1, Wfc, bfc, out);
}

// round 12
// speedup vs baseline: 1.1140x; 1.1140x over previous
#include <cuda_runtime.h>
#include <cstdint>

#define B_SZ 1024
#define T_SZ 512
#define F_SZ 124
#define NROWS (B_SZ * T_SZ)

// Pre-activations of layer0, [b][t] as float4 (xyz = hidden, w = pad). 8.4MB -> L2.
// [b][t] makes pre_kernel's write perfectly coalesced (row = b*T + t).
__device__ float4 g_pre[NROWS];

__device__ __forceinline__ float tanha(float v) {
    float r;
    asm("tanh.approx.f32 %0, %1;" : "=f"(r) : "f"(v));
    return r;
}
__device__ __forceinline__ void cp_async16(unsigned int saddr, const void* gptr) {
    asm volatile("cp.async.cg.shared.global [%0], [%1], 16;" :: "r"(saddr), "l"(gptr));
}
#define CP_COMMIT() asm volatile("cp.async.commit_group;" ::: "memory")
#define CP_WAIT1()  asm volatile("cp.async.wait_group 1;"  ::: "memory")

// packed f32x2 helpers (FFMA2 — only reachable via PTX fma.rn.f32x2)
typedef unsigned long long ull;
__device__ __forceinline__ ull pk2(float lo, float hi) {
    ull r; asm("mov.b64 %0, {%1, %2};" : "=l"(r) : "f"(lo), "f"(hi)); return r;
}
__device__ __forceinline__ void unpk2(float& lo, float& hi, ull v) {
    asm("mov.b64 {%0, %1}, %2;" : "=f"(lo), "=f"(hi) : "l"(v));
}
__device__ __forceinline__ ull fma2(ull a, ull b, ull c) {
    ull d; asm("fma.rn.f32x2 %0, %1, %2, %3;" : "=l"(d) : "l"(a), "l"(b), "l"(c)); return d;
}

// ---------------------------------------------------------------------------
// Kernel A: pre[b][t][i] = dot(x[b,t,:], W_ih0[i,:]) + biases.
// cp.async double-buffered (chunk k+2 in flight while chunk k computes).
// Output write is now CONTIGUOUS: g_pre[row0 + tid], 4KB per block.
// ---------------------------------------------------------------------------
extern __shared__ float s2[];            // [2][256*36] = 73728 B dynamic

__global__ __launch_bounds__(256) void pre_kernel(
    const float* __restrict__ x,
    const float* __restrict__ Wih0,
    const float* __restrict__ bih0,
    const float* __restrict__ bhh0)
{
    __shared__ float sW[3 * 128];        // W_ih0 zero-padded to 128 cols

    const int tid  = threadIdx.x;
    const int row0 = blockIdx.x * 256;
    const int lane = tid & 31;
    const int lrbase = (tid >> 5) * 32 + (lane >> 3);
    const int c4     = lane & 7;
    const float4* __restrict__ x4 = (const float4*)x;   // row stride 31 float4

#define STAGE_PRE(bufidx, kc, nc4)                                         \
    if (c4 < (nc4)) {                                                      \
        _Pragma("unroll")                                                  \
        for (int it = 0; it < 8; it++) {                                   \
            const int lr = lrbase + it * 4;                                \
            unsigned int sa = (unsigned int)__cvta_generic_to_shared(      \
                &s2[(bufidx) * 9216 + lr * 36 + c4 * 4]);                  \
            cp_async16(sa, &x4[(row0 + lr) * 31 + ((kc) >> 2) + c4]);      \
        }                                                                  \
    }

    // Start DRAM traffic immediately: chunks 0 and 1 in flight.
    STAGE_PRE(0, 0, 8);  CP_COMMIT();
    STAGE_PRE(1, 32, 8); CP_COMMIT();

    for (int idx = tid; idx < 3 * 128; idx += 256) {
        int i = idx >> 7, cc = idx & 127;
        sW[idx] = (cc < F_SZ) ? Wih0[i * F_SZ + cc] : 0.0f;
    }
    const float bs0 = bih0[0] + bhh0[0];
    const float bs1 = bih0[1] + bhh0[1];
    const float bs2 = bih0[2] + bhh0[2];
    __syncthreads();

    float acc0 = 0.f, acc1 = 0.f, acc2 = 0.f;

    #pragma unroll
    for (int ci = 0; ci < 4; ci++) {
        const int kc  = ci * 32;
        const int nc4 = (ci == 3) ? 7 : 8;

        CP_WAIT1();          // chunk ci complete (ci+1 may still be in flight)
        __syncwarp();        // other lanes' cp.async writes visible

        const float* sb = &s2[(ci & 1) * 9216];
        #pragma unroll
        for (int cc = 0; cc < 8; cc++) {
            if (cc < nc4) {
                float4 v  = *(const float4*)&sb[tid * 36 + cc * 4];
                float4 w0 = *(const float4*)&sW[0 * 128 + kc + cc * 4];
                float4 w1 = *(const float4*)&sW[1 * 128 + kc + cc * 4];
                float4 w2 = *(const float4*)&sW[2 * 128 + kc + cc * 4];
                acc0 += v.x * w0.x + v.y * w0.y + v.z * w0.z + v.w * w0.w;
                acc1 += v.x * w1.x + v.y * w1.y + v.z * w1.z + v.w * w1.w;
                acc2 += v.x * w2.x + v.y * w2.y + v.z * w2.z + v.w * w2.w;
            }
        }
        __syncwarp();        // compute done before re-staging this buffer

        if (ci < 2) {
            const int kn = (ci + 2) * 32;
            const int nn = (ci + 2 == 3) ? 7 : 8;
            STAGE_PRE(ci & 1, kn, nn);
        }
        CP_COMMIT();         // possibly-empty group keeps wait counts aligned
    }

    // row = b*T + t and g_pre is [b][t] -> contiguous block write.
    g_pre[row0 + tid] = make_float4(acc0 + bs0, acc1 + bs1, acc2 + bs2, 0.0f);
}
#undef STAGE_PRE

// ---------------------------------------------------------------------------
// Kernel B: fused 2-layer recurrence, 32 blocks x 1 warp, ZERO barriers.
// Each lane owns one batch element: self-feeds its contiguous pre-stream
// (g_pre[b][t]) through a private 3-stage cp.async ring slot and runs both
// layers. Layer-1 math uses packed fma.rn.f32x2 (verified in R10).
// Lane reads only smem it staged itself -> wait_group is the only sync.
// ---------------------------------------------------------------------------
#define CH    16
#define NST   3
#define NCHK  (T_SZ / CH)               // 32

__global__ __launch_bounds__(32) void rnn_kernel(
    const float* __restrict__ Whh0,
    const float* __restrict__ Wih1,
    const float* __restrict__ Whh1,
    const float* __restrict__ bih1,
    const float* __restrict__ bhh1,
    const float* __restrict__ Wfc,
    const float* __restrict__ bfc,
    float* __restrict__ out)
{
    __shared__ float4 ring[NST * CH * 32];    // 24 KB, [stage][step][lane]

    const int lane = threadIdx.x;
    const int b    = blockIdx.x * 32 + lane;
    const float4* __restrict__ gsrc = g_pre + (size_t)b * T_SZ;   // contiguous per lane

    // layer-0 weights (scalar)
    const float a0 = Whh0[0], a1 = Whh0[1], a2 = Whh0[2];
    const float a3 = Whh0[3], a4 = Whh0[4], a5 = Whh0[5];
    const float a6 = Whh0[6], a7 = Whh0[7], a8 = Whh0[8];

    // layer-1 weights: rows 0,1 packed for fma2; row 2 scalar
    const float bb0 = bih1[0] + bhh1[0];
    const float bb1 = bih1[1] + bhh1[1];
    const float bb2 = bih1[2] + bhh1[2];
    const ull Dx01 = pk2(Whh1[0], Whh1[3]), Dy01 = pk2(Whh1[1], Whh1[4]), Dz01 = pk2(Whh1[2], Whh1[5]);
    const ull Cx01 = pk2(Wih1[0], Wih1[3]), Cy01 = pk2(Wih1[1], Wih1[4]), Cz01 = pk2(Wih1[2], Wih1[5]);
    const ull BB01 = pk2(bb0, bb1);
    const float d6 = Whh1[6], d7 = Whh1[7], d8 = Whh1[8];
    const float c6 = Wih1[6], c7 = Wih1[7], c8 = Wih1[8];

    float h0x = 0.f, h0y = 0.f, h0z = 0.f;
    float h1x = 0.f, h1y = 0.f, h1z = 0.f;
    ull hx2 = pk2(0.f, 0.f), hy2 = hx2, hz2 = hx2;

    // prologue: chunks 0,1 in flight (lane stages only its own column)
    #pragma unroll
    for (int c = 0; c < 2; c++) {
        #pragma unroll
        for (int s = 0; s < CH; s++) {
            unsigned int sa = (unsigned int)__cvta_generic_to_shared(
                &ring[(c * CH + s) * 32 + lane]);
            cp_async16(sa, gsrc + c * CH + s);
        }
        CP_COMMIT();
    }

    for (int c = 0; c < NCHK; c++) {
        CP_WAIT1();                       // chunk c landed (self-staged, self-read)

        // stage chunk c+2 first so its L2 traffic overlaps this chunk's math
        const int cn = c + 2;
        if (cn < NCHK) {
            const int st = cn % NST;
            #pragma unroll
            for (int s = 0; s < CH; s++) {
                unsigned int sa = (unsigned int)__cvta_generic_to_shared(
                    &ring[(st * CH + s) * 32 + lane]);
                cp_async16(sa, gsrc + cn * CH + s);
            }
        }
        CP_COMMIT();                      // possibly-empty; keeps wait counts aligned

        const float4* pr = &ring[(c % NST) * CH * 32];
        #pragma unroll
        for (int s = 0; s < CH; s++) {
            const float4 p = pr[s * 32 + lane];

            // layer 0
            const float n0x = tanha(p.x + a0 * h0x + a1 * h0y + a2 * h0z);
            const float n0y = tanha(p.y + a3 * h0x + a4 * h0y + a5 * h0z);
            const float n0z = tanha(p.z + a6 * h0x + a7 * h0y + a8 * h0z);

            // layer 1 (rows 0,1 packed; row 2 scalar)
            const ull px2 = pk2(n0x, n0x);
            const ull py2 = pk2(n0y, n0y);
            const ull pz2 = pk2(n0z, n0z);
            ull T = fma2(Dx01, hx2, BB01);
            T = fma2(Dy01, hy2, T);
            T = fma2(Dz01, hz2, T);
            T = fma2(Cx01, px2, T);
            T = fma2(Cy01, py2, T);
            T = fma2(Cz01, pz2, T);
            float t2 = bb2 + d6 * h1x + d7 * h1y + d8 * h1z;
            t2 += c6 * n0x + c7 * n0y + c8 * n0z;
            float t0, t1; unpk2(t0, t1, T);
            h1x = tanha(t0); h1y = tanha(t1); h1z = tanha(t2);
            hx2 = pk2(h1x, h1x); hy2 = pk2(h1y, h1y); hz2 = pk2(h1z, h1z);

            h0x = n0x; h0y = n0y; h0z = n0z;
        }
    }

    #pragma unroll
    for (int o = 0; o < 6; o++) {
        out[b * 6 + o] = bfc[o] + Wfc[o * 3 + 0] * h1x
                                + Wfc[o * 3 + 1] * h1y
                                + Wfc[o * 3 + 2] * h1z;
    }
}

extern "C" void kernel_launch(void* const* d_in, const int* in_sizes, int n_in,
                              void* d_out, int out_size)
{
    (void)in_sizes; (void)n_in; (void)out_size;
    const float* x    = (const float*)d_in[0];
    const float* Wih0 = (const float*)d_in[1];
    const float* Whh0 = (const float*)d_in[2];
    const float* bih0 = (const float*)d_in[3];
    const float* bhh0 = (const float*)d_in[4];
    const float* Wih1 = (const float*)d_in[5];
    const float* Whh1 = (const float*)d_in[6];
    const float* bih1 = (const float*)d_in[7];
    const float* bhh1 = (const float*)d_in[8];
    const float* Wfc  = (const float*)d_in[9];
    const float* bfc  = (const float*)d_in[10];
    float* out = (float*)d_out;

    // Idempotent, safe under graph capture, no static guard.
    const int pre_smem = 2 * 256 * 36 * sizeof(float);   // 73728 B
    cudaFuncSetAttribute(pre_kernel, cudaFuncAttributeMaxDynamicSharedMemorySize, pre_smem);

    pre_kernel<<<NROWS / 256, 256, pre_smem>>>(x, Wih0, bih0, bhh0);
    rnn_kernel<<<B_SZ / 32, 32>>>(Whh0, Wih1, Whh1, bih1, bhh1, Wfc, bfc, out);
}

// round 14
// speedup vs baseline: 1.1832x; 1.0621x over previous
#include <cuda_runtime.h>
#include <cstdint>

#define B_SZ 1024
#define T_SZ 512
#define F_SZ 124
#define NROWS (B_SZ * T_SZ)

// Pre-activations of layer0, [b][t] as float4 (xyz = hidden, w = pad). 8.4MB -> L2.
__device__ float4 g_pre[NROWS];

__device__ __forceinline__ float tanha(float v) {
    float r;
    asm("tanh.approx.f32 %0, %1;" : "=f"(r) : "f"(v));
    return r;
}
__device__ __forceinline__ void cp_async16(unsigned int saddr, const void* gptr) {
    asm volatile("cp.async.cg.shared.global [%0], [%1], 16;" :: "r"(saddr), "l"(gptr));
}
#define CP_COMMIT() asm volatile("cp.async.commit_group;" ::: "memory")
#define CP_WAIT1()  asm volatile("cp.async.wait_group 1;"  ::: "memory")

// ---------------------------------------------------------------------------
// Kernel A: pre[b][t][i] = dot(x[b,t,:], W_ih0[i,:]) + biases.  (unchanged R11)
// ---------------------------------------------------------------------------
extern __shared__ float s2[];            // [2][256*36] = 73728 B dynamic

__global__ __launch_bounds__(256) void pre_kernel(
    const float* __restrict__ x,
    const float* __restrict__ Wih0,
    const float* __restrict__ bih0,
    const float* __restrict__ bhh0)
{
    __shared__ float sW[3 * 128];        // W_ih0 zero-padded to 128 cols

    const int tid  = threadIdx.x;
    const int row0 = blockIdx.x * 256;
    const int lane = tid & 31;
    const int lrbase = (tid >> 5) * 32 + (lane >> 3);
    const int c4     = lane & 7;
    const float4* __restrict__ x4 = (const float4*)x;   // row stride 31 float4

#define STAGE_PRE(bufidx, kc, nc4)                                         \
    if (c4 < (nc4)) {                                                      \
        _Pragma("unroll")                                                  \
        for (int it = 0; it < 8; it++) {                                   \
            const int lr = lrbase + it * 4;                                \
            unsigned int sa = (unsigned int)__cvta_generic_to_shared(      \
                &s2[(bufidx) * 9216 + lr * 36 + c4 * 4]);                  \
            cp_async16(sa, &x4[(row0 + lr) * 31 + ((kc) >> 2) + c4]);      \
        }                                                                  \
    }

    STAGE_PRE(0, 0, 8);  CP_COMMIT();
    STAGE_PRE(1, 32, 8); CP_COMMIT();

    for (int idx = tid; idx < 3 * 128; idx += 256) {
        int i = idx >> 7, cc = idx & 127;
        sW[idx] = (cc < F_SZ) ? Wih0[i * F_SZ + cc] : 0.0f;
    }
    const float bs0 = bih0[0] + bhh0[0];
    const float bs1 = bih0[1] + bhh0[1];
    const float bs2 = bih0[2] + bhh0[2];
    __syncthreads();

    float acc0 = 0.f, acc1 = 0.f, acc2 = 0.f;

    #pragma unroll
    for (int ci = 0; ci < 4; ci++) {
        const int kc  = ci * 32;
        const int nc4 = (ci == 3) ? 7 : 8;

        CP_WAIT1();
        __syncwarp();

        const float* sb = &s2[(ci & 1) * 9216];
        #pragma unroll
        for (int cc = 0; cc < 8; cc++) {
            if (cc < nc4) {
                float4 v  = *(const float4*)&sb[tid * 36 + cc * 4];
                float4 w0 = *(const float4*)&sW[0 * 128 + kc + cc * 4];
                float4 w1 = *(const float4*)&sW[1 * 128 + kc + cc * 4];
                float4 w2 = *(const float4*)&sW[2 * 128 + kc + cc * 4];
                acc0 += v.x * w0.x + v.y * w0.y + v.z * w0.z + v.w * w0.w;
                acc1 += v.x * w1.x + v.y * w1.y + v.z * w1.z + v.w * w1.w;
                acc2 += v.x * w2.x + v.y * w2.y + v.z * w2.z + v.w * w2.w;
            }
        }
        __syncwarp();

        if (ci < 2) {
            const int kn = (ci + 2) * 32;
            const int nn = (ci + 2 == 3) ? 7 : 8;
            STAGE_PRE(ci & 1, kn, nn);
        }
        CP_COMMIT();
    }

    g_pre[row0 + tid] = make_float4(acc0 + bs0, acc1 + bs1, acc2 + bs2, 0.0f);
}
#undef STAGE_PRE

// ---------------------------------------------------------------------------
// Kernel B: fused recurrence, software-pipelined one step:
//   body(s) computes { L0(s),  L1(s-1) } — the two are INDEPENDENT
//   (L1(s-1) uses n0(s-1) & h1(s-2); L0(s) uses p(s) & n0(s-1)),
//   so their FFMA/MUFU streams interleave and hide each other's latency.
// All-scalar; C-part of L1 precomputed off the h1 chain; D-part last
// => both recurrent cycles are 3 FFMA + tanh = 28 cyc. MUFU floor 48/step.
// 32 blocks x 1 warp, zero barriers, private cp.async ring per lane.
// ---------------------------------------------------------------------------
#define CH    16
#define NST   3
#define NCHK  (T_SZ / CH)               // 32

__global__ __launch_bounds__(32) void rnn_kernel(
    const float* __restrict__ Whh0,
    const float* __restrict__ Wih1,
    const float* __restrict__ Whh1,
    const float* __restrict__ bih1,
    const float* __restrict__ bhh1,
    const float* __restrict__ Wfc,
    const float* __restrict__ bfc,
    float* __restrict__ out)
{
    __shared__ float4 ring[NST * CH * 32];    // 24 KB, [stage][step][lane]

    const int lane = threadIdx.x;
    const int b    = blockIdx.x * 32 + lane;
    const float4* __restrict__ gsrc = g_pre + (size_t)b * T_SZ;

    const float a0 = Whh0[0], a1 = Whh0[1], a2 = Whh0[2];
    const float a3 = Whh0[3], a4 = Whh0[4], a5 = Whh0[5];
    const float a6 = Whh0[6], a7 = Whh0[7], a8 = Whh0[8];
    const float c0 = Wih1[0], c1 = Wih1[1], c2 = Wih1[2];
    const float c3 = Wih1[3], c4 = Wih1[4], c5 = Wih1[5];
    const float c6 = Wih1[6], c7 = Wih1[7], c8 = Wih1[8];
    const float d0 = Whh1[0], d1 = Whh1[1], d2 = Whh1[2];
    const float d3 = Whh1[3], d4 = Whh1[4], d5 = Whh1[5];
    const float d6 = Whh1[6], d7 = Whh1[7], d8 = Whh1[8];
    const float bb0 = bih1[0] + bhh1[0];
    const float bb1 = bih1[1] + bhh1[1];
    const float bb2 = bih1[2] + bhh1[2];

    // n0* = L0 output of the previous step (doubles as h0 state).
    float n0x = 0.f, n0y = 0.f, n0z = 0.f;
    float h1x = 0.f, h1y = 0.f, h1z = 0.f;

    // ---- dual body: L1 for previous step (using old n0), L0 for this step ----
#define L1_PREV()                                                          \
    {                                                                      \
        /* C-part + bias: off the h1 chain (n0 ready since last body) */   \
        const float S0 = fmaf(c0, n0x, fmaf(c1, n0y, fmaf(c2, n0z, bb0))); \
        const float S1 = fmaf(c3, n0x, fmaf(c4, n0y, fmaf(c5, n0z, bb1))); \
        const float S2 = fmaf(c6, n0x, fmaf(c7, n0y, fmaf(c8, n0z, bb2))); \
        /* D-part last: h1 recurrent chain = 3 FFMA + tanh */              \
        const float t0 = fmaf(d0, h1x, fmaf(d1, h1y, fmaf(d2, h1z, S0)));  \
        const float t1 = fmaf(d3, h1x, fmaf(d4, h1y, fmaf(d5, h1z, S1)));  \
        const float t2 = fmaf(d6, h1x, fmaf(d7, h1y, fmaf(d8, h1z, S2)));  \
        h1x = tanha(t0); h1y = tanha(t1); h1z = tanha(t2);                 \
    }

#define L0_CUR(p)                                                          \
    {                                                                      \
        const float m0 = fmaf(a0, n0x, fmaf(a1, n0y, fmaf(a2, n0z, (p).x))); \
        const float m1 = fmaf(a3, n0x, fmaf(a4, n0y, fmaf(a5, n0z, (p).y))); \
        const float m2 = fmaf(a6, n0x, fmaf(a7, n0y, fmaf(a8, n0z, (p).z))); \
        const float nx = tanha(m0), ny = tanha(m1), nz = tanha(m2);        \
        n0x = nx; n0y = ny; n0z = nz;                                      \
    }

    // prologue: chunks 0,1 in flight
    #pragma unroll
    for (int c = 0; c < 2; c++) {
        #pragma unroll
        for (int s = 0; s < CH; s++) {
            unsigned int sa = (unsigned int)__cvta_generic_to_shared(
                &ring[(c * CH + s) * 32 + lane]);
            cp_async16(sa, gsrc + c * CH + s);
        }
        CP_COMMIT();
    }

    // ---- chunk 0: peel step 0 (no L1 before the first L0) ----
    {
        CP_WAIT1();
        // stage chunk 2
        #pragma unroll
        for (int s = 0; s < CH; s++) {
            unsigned int sa = (unsigned int)__cvta_generic_to_shared(
                &ring[(2 % NST) * CH * 32 + s * 32 + lane]);
            cp_async16(sa, gsrc + 2 * CH + s);
        }
        CP_COMMIT();

        const float4* pr = &ring[0];
        { const float4 p = pr[0 * 32 + lane]; L0_CUR(p); }
        #pragma unroll
        for (int s = 1; s < CH; s++) {
            const float4 p = pr[s * 32 + lane];
            L1_PREV();      // h1(s-1) from n0(s-1), h1(s-2)
            L0_CUR(p);      // n0(s)   from p(s), n0(s-1)  — independent of L1 above
        }
    }

    // ---- chunks 1..31 ----
    for (int c = 1; c < NCHK; c++) {
        CP_WAIT1();
        const int cn = c + 2;
        if (cn < NCHK) {
            const int st = cn % NST;
            #pragma unroll
            for (int s = 0; s < CH; s++) {
                unsigned int sa = (unsigned int)__cvta_generic_to_shared(
                    &ring[(st * CH + s) * 32 + lane]);
                cp_async16(sa, gsrc + cn * CH + s);
            }
        }
        CP_COMMIT();

        const float4* pr = &ring[(c % NST) * CH * 32];
        #pragma unroll
        for (int s = 0; s < CH; s++) {
            const float4 p = pr[s * 32 + lane];
            L1_PREV();
            L0_CUR(p);
        }
    }

    // epilogue: L1 for the final step
    L1_PREV();

#undef L1_PREV
#undef L0_CUR

    #pragma unroll
    for (int o = 0; o < 6; o++) {
        out[b * 6 + o] = bfc[o] + Wfc[o * 3 + 0] * h1x
                                + Wfc[o * 3 + 1] * h1y
                                + Wfc[o * 3 + 2] * h1z;
    }
}

extern "C" void kernel_launch(void* const* d_in, const int* in_sizes, int n_in,
                              void* d_out, int out_size)
{
    (void)in_sizes; (void)n_in; (void)out_size;
    const float* x    = (const float*)d_in[0];
    const float* Wih0 = (const float*)d_in[1];
    const float* Whh0 = (const float*)d_in[2];
    const float* bih0 = (const float*)d_in[3];
    const float* bhh0 = (const float*)d_in[4];
    const float* Wih1 = (const float*)d_in[5];
    const float* Whh1 = (const float*)d_in[6];
    const float* bih1 = (const float*)d_in[7];
    const float* bhh1 = (const float*)d_in[8];
    const float* Wfc  = (const float*)d_in[9];
    const float* bfc  = (const float*)d_in[10];
    float* out = (float*)d_out;

    const int pre_smem = 2 * 256 * 36 * sizeof(float);   // 73728 B
    cudaFuncSetAttribute(pre_kernel, cudaFuncAttributeMaxDynamicSharedMemorySize, pre_smem);

    pre_kernel<<<NROWS / 256, 256, pre_smem>>>(x, Wih0, bih0, bhh0);
    rnn_kernel<<<B_SZ / 32, 32>>>(Whh0, Wih1, Whh1, bih1, bhh1, Wfc, bfc, out);
}